// round 1
// baseline (speedup 1.0000x reference)
#include <cuda_runtime.h>
#include <cuda_bf16.h>

// Problem shapes (fixed by setup_inputs)
#define B    128
#define N1   32
#define N2   32
#define D1   23
#define D2   13
#define NN   64      // N1+N2
#define E    72
#define H    256
#define F    128
#define TWOE 144
#define LNCNT 4608   // NN*E

// Scratch (no allocation allowed -> __device__ globals)
__device__ float g_a[B * NN * E];          // layernormed embeddings   [B,64,72]
__device__ float g_u[B * NN * H];          // a @ Wg_top + b_g         [8192,256]
__device__ float g_v[B * NN * H];          // a @ Wg_bot               [8192,256]
__device__ float g_p[B * NN * H];          // per-(b,i) partial sums   [8192,256]

// ---------------------------------------------------------------------------
// K1: fused split-embedding + joint LayerNorm over (N,E) per batch.
// One block per b, 256 threads, 18 elements each (18*256 = 4608).
// ---------------------------------------------------------------------------
__global__ __launch_bounds__(256) void k_embed_ln(
    const float* __restrict__ xa, const float* __restrict__ xb,
    const float* __restrict__ Wa, const float* __restrict__ ba,
    const float* __restrict__ Wb, const float* __restrict__ bb,
    const float* __restrict__ g0, const float* __restrict__ b0)
{
    const int b   = blockIdx.x;
    const int tid = threadIdx.x;
    __shared__ float rsum[8], rssq[8];
    __shared__ float s_mean, s_rstd;

    float vals[18];
    float sum = 0.f, ssq = 0.f;

    #pragma unroll
    for (int c = 0; c < 18; ++c) {
        const int idx = tid + c * 256;      // < 4608
        const int n = idx / E;
        const int e = idx - n * E;
        float acc;
        if (n < N1) {
            acc = ba[e];
            const float* xr = xa + (b * N1 + n) * D1;
            #pragma unroll
            for (int k = 0; k < D1; ++k) acc = fmaf(xr[k], Wa[k * E + e], acc);
        } else {
            acc = bb[e];
            const float* xr = xb + (b * N2 + (n - N1)) * D2;
            #pragma unroll
            for (int k = 0; k < D2; ++k) acc = fmaf(xr[k], Wb[k * E + e], acc);
        }
        vals[c] = acc;
        sum += acc;
        ssq = fmaf(acc, acc, ssq);
    }

    // block reduce (8 warps)
    #pragma unroll
    for (int o = 16; o; o >>= 1) {
        sum += __shfl_xor_sync(~0u, sum, o);
        ssq += __shfl_xor_sync(~0u, ssq, o);
    }
    const int w = tid >> 5, lane = tid & 31;
    if (lane == 0) { rsum[w] = sum; rssq[w] = ssq; }
    __syncthreads();
    if (tid == 0) {
        float s = 0.f, q = 0.f;
        #pragma unroll
        for (int i = 0; i < 8; ++i) { s += rsum[i]; q += rssq[i]; }
        const float mean = s * (1.f / LNCNT);
        const float var  = fmaf(q, 1.f / LNCNT, -mean * mean);
        s_mean = mean;
        s_rstd = rsqrtf(var + 1e-5f);
    }
    __syncthreads();
    const float mean = s_mean, rstd = s_rstd;

    #pragma unroll
    for (int c = 0; c < 18; ++c) {
        const int idx = tid + c * 256;
        const float y = (vals[c] - mean) * rstd * g0[idx] + b0[idx];
        g_a[b * LNCNT + idx] = y;
    }
}

// ---------------------------------------------------------------------------
// K2: u = a @ Wg[0:72] + b_g ; v = a @ Wg[72:144]
// One block per row m = b*64+n (8192 blocks), 256 threads (one per h).
// ---------------------------------------------------------------------------
__global__ __launch_bounds__(256) void k_uv(
    const float* __restrict__ Wg, const float* __restrict__ bg)
{
    const int m = blockIdx.x;
    const int h = threadIdx.x;
    __shared__ float sa[E];
    if (h < E) sa[h] = g_a[m * E + h];
    __syncthreads();

    float u = bg[h];
    float v = 0.f;
    #pragma unroll
    for (int k = 0; k < E; ++k) {
        const float a = sa[k];
        u = fmaf(a, Wg[k * H + h], u);
        v = fmaf(a, Wg[(E + k) * H + h], v);
    }
    g_u[m * H + h] = u;
    g_v[m * H + h] = v;
}

// ---------------------------------------------------------------------------
// K3: pairwise stage.  g_pre[b,i,j,:] = u[b,i] + v[b,j];
//     g = LN_H(ELU(g_pre)); partial[b,i,:] = sum_j g.
// One warp per (b,i), lane holds 8 channels [lane*8, lane*8+8).
// Block = 8 warps sharing one b (v[b] staged in 64KB dynamic smem).
// Grid = B*8 = 1024 blocks.
// ---------------------------------------------------------------------------
__global__ __launch_bounds__(256) void k_pair(
    const float* __restrict__ lg, const float* __restrict__ lb)
{
    extern __shared__ float sv[];               // [64*256] = v[b]
    const int b    = blockIdx.x >> 3;
    const int ig   = blockIdx.x & 7;
    const int tid  = threadIdx.x;
    const int w    = tid >> 5;
    const int lane = tid & 31;

    // stage v[b] into shared (vectorized)
    {
        const float4* vb = (const float4*)(g_v + b * NN * H);
        float4* s4 = (float4*)sv;
        #pragma unroll
        for (int t = tid; t < NN * H / 4; t += 256) s4[t] = vb[t];
    }

    const int i  = ig * 8 + w;
    const int m  = b * NN + i;
    const int c0 = lane * 8;

    float ru[8], cg[8], cb[8], acc[8];
    {
        const float4 u0 = *(const float4*)(g_u + m * H + c0);
        const float4 u1 = *(const float4*)(g_u + m * H + c0 + 4);
        ru[0]=u0.x; ru[1]=u0.y; ru[2]=u0.z; ru[3]=u0.w;
        ru[4]=u1.x; ru[5]=u1.y; ru[6]=u1.z; ru[7]=u1.w;
        const float4 a0 = *(const float4*)(lg + c0);
        const float4 a1 = *(const float4*)(lg + c0 + 4);
        cg[0]=a0.x; cg[1]=a0.y; cg[2]=a0.z; cg[3]=a0.w;
        cg[4]=a1.x; cg[5]=a1.y; cg[6]=a1.z; cg[7]=a1.w;
        const float4 b0v = *(const float4*)(lb + c0);
        const float4 b1v = *(const float4*)(lb + c0 + 4);
        cb[0]=b0v.x; cb[1]=b0v.y; cb[2]=b0v.z; cb[3]=b0v.w;
        cb[4]=b1v.x; cb[5]=b1v.y; cb[6]=b1v.z; cb[7]=b1v.w;
    }
    #pragma unroll
    for (int r = 0; r < 8; ++r) acc[r] = 0.f;

    __syncthreads();

    for (int j = 0; j < NN; ++j) {
        const float4 v0 = *(const float4*)&sv[j * H + c0];
        const float4 v1 = *(const float4*)&sv[j * H + c0 + 4];
        float vv[8] = {v0.x, v0.y, v0.z, v0.w, v1.x, v1.y, v1.z, v1.w};

        float ee[8];
        float sum = 0.f, ssq = 0.f;
        #pragma unroll
        for (int r = 0; r < 8; ++r) {
            const float t = ru[r] + vv[r];
            const float e = (t > 0.f) ? t : (__expf(t) - 1.f);
            ee[r] = e;
            sum += e;
            ssq = fmaf(e, e, ssq);
        }
        #pragma unroll
        for (int o = 16; o; o >>= 1) {
            sum += __shfl_xor_sync(~0u, sum, o);
            ssq += __shfl_xor_sync(~0u, ssq, o);
        }
        const float mean = sum * (1.f / H);
        const float var  = fmaf(ssq, 1.f / H, -mean * mean);
        const float A    = rsqrtf(var + 1e-5f);
        const float mA   = mean * A;
        #pragma unroll
        for (int r = 0; r < 8; ++r)
            acc[r] = fmaf(cg[r], fmaf(ee[r], A, -mA), acc[r]);
    }

    // fold the beta contribution (64 * cb per channel), store partial
    float4 o0, o1;
    o0.x = fmaf(64.f, cb[0], acc[0]); o0.y = fmaf(64.f, cb[1], acc[1]);
    o0.z = fmaf(64.f, cb[2], acc[2]); o0.w = fmaf(64.f, cb[3], acc[3]);
    o1.x = fmaf(64.f, cb[4], acc[4]); o1.y = fmaf(64.f, cb[5], acc[5]);
    o1.z = fmaf(64.f, cb[6], acc[6]); o1.w = fmaf(64.f, cb[7], acc[7]);
    *(float4*)(g_p + m * H + c0)     = o0;
    *(float4*)(g_p + m * H + c0 + 4) = o1;
}

// ---------------------------------------------------------------------------
// K4: s[b,:] = sum_i partial[b,i,:];  out[b,:] = ELU(s @ W_f + b_f)
// One block per b, deterministic (no atomics).
// ---------------------------------------------------------------------------
__global__ __launch_bounds__(256) void k_final(
    const float* __restrict__ Wf, const float* __restrict__ bf,
    float* __restrict__ out)
{
    const int b   = blockIdx.x;
    const int tid = threadIdx.x;
    __shared__ float ss[H];

    const float* p = g_p + b * NN * H;
    float s = 0.f;
    #pragma unroll 8
    for (int i = 0; i < NN; ++i) s += p[i * H + tid];
    ss[tid] = s;
    __syncthreads();

    if (tid < F) {
        float o = bf[tid];
        #pragma unroll 8
        for (int h = 0; h < H; ++h) o = fmaf(ss[h], Wf[h * F + tid], o);
        out[b * F + tid] = (o > 0.f) ? o : expm1f(o);
    }
}

// ---------------------------------------------------------------------------
extern "C" void kernel_launch(void* const* d_in, const int* in_sizes, int n_in,
                              void* d_out, int out_size)
{
    const float* x_a   = (const float*)d_in[0];
    const float* x_b   = (const float*)d_in[1];
    const float* W_a   = (const float*)d_in[2];
    const float* b_a   = (const float*)d_in[3];
    const float* W_b   = (const float*)d_in[4];
    const float* b_b   = (const float*)d_in[5];
    const float* ln0_g = (const float*)d_in[6];
    const float* ln0_b = (const float*)d_in[7];
    const float* W_g   = (const float*)d_in[8];
    const float* b_g   = (const float*)d_in[9];
    const float* lng_g = (const float*)d_in[10];
    const float* lng_b = (const float*)d_in[11];
    const float* W_f   = (const float*)d_in[12];
    const float* b_f   = (const float*)d_in[13];
    float* out = (float*)d_out;

    k_embed_ln<<<B, 256>>>(x_a, x_b, W_a, b_a, W_b, b_b, ln0_g, ln0_b);
    k_uv<<<B * NN, 256>>>(W_g, b_g);

    static const size_t smem = NN * H * sizeof(float);   // 64 KB
    cudaFuncSetAttribute(k_pair, cudaFuncAttributeMaxDynamicSharedMemorySize, (int)smem);
    k_pair<<<B * 8, 256, smem>>>(lng_g, lng_b);

    k_final<<<B, 256>>>(W_f, b_f, out);
}

// round 2
// speedup vs baseline: 1.4365x; 1.4365x over previous
#include <cuda_runtime.h>
#include <cuda_bf16.h>

#define B    128
#define N1   32
#define N2   32
#define D1   23
#define D2   13
#define NN   64
#define E    72
#define H    256
#define F    128
#define LNCNT 4608

typedef unsigned long long u64;

// ---- f32x2 packed helpers (sm_103a; ptxas never emits these from C++) ----
__device__ __forceinline__ u64 pk(float lo, float hi) {
    u64 r; asm("mov.b64 %0, {%1,%2};" : "=l"(r) : "f"(lo), "f"(hi)); return r;
}
__device__ __forceinline__ void upk(u64 x, float& lo, float& hi) {
    asm("mov.b64 {%0,%1}, %2;" : "=f"(lo), "=f"(hi) : "l"(x));
}
__device__ __forceinline__ u64 add2(u64 a, u64 b) {
    u64 d; asm("add.rn.f32x2 %0,%1,%2;" : "=l"(d) : "l"(a), "l"(b)); return d;
}
__device__ __forceinline__ u64 mul2(u64 a, u64 b) {
    u64 d; asm("mul.rn.f32x2 %0,%1,%2;" : "=l"(d) : "l"(a), "l"(b)); return d;
}
__device__ __forceinline__ u64 fma2(u64 a, u64 b, u64 c) {
    u64 d; asm("fma.rn.f32x2 %0,%1,%2,%3;" : "=l"(d) : "l"(a), "l"(b), "l"(c)); return d;
}
__device__ __forceinline__ float ex2f(float x) {
    float r; asm("ex2.approx.ftz.f32 %0, %1;" : "=f"(r) : "f"(x)); return r;
}

// Scratch (__device__ globals; no allocation allowed)
__device__ float g_a[B * NN * E];      // layernormed embeddings [B,64,72]
__device__ float g_u[B * NN * H];      // a @ Wg_top + b_g
__device__ float g_v[B * NN * H];      // a @ Wg_bot
__device__ float g_p[B * 8 * H];       // per-block (8 i's) partials [1024,256]

// ---------------------------------------------------------------------------
// K1: split-embedding + joint LayerNorm over (N,E). One block per b.
// ---------------------------------------------------------------------------
__global__ __launch_bounds__(256) void k_embed_ln(
    const float* __restrict__ xa, const float* __restrict__ xb,
    const float* __restrict__ Wa, const float* __restrict__ ba,
    const float* __restrict__ Wb, const float* __restrict__ bb,
    const float* __restrict__ g0, const float* __restrict__ b0)
{
    const int b   = blockIdx.x;
    const int tid = threadIdx.x;
    __shared__ float rsum[8], rssq[8];
    __shared__ float s_mean, s_rstd;

    float vals[18];
    float sum = 0.f, ssq = 0.f;

    #pragma unroll
    for (int c = 0; c < 18; ++c) {
        const int idx = tid + c * 256;
        const int n = idx / E;
        const int e = idx - n * E;
        float acc;
        if (n < N1) {
            acc = ba[e];
            const float* xr = xa + (b * N1 + n) * D1;
            #pragma unroll
            for (int k = 0; k < D1; ++k) acc = fmaf(xr[k], Wa[k * E + e], acc);
        } else {
            acc = bb[e];
            const float* xr = xb + (b * N2 + (n - N1)) * D2;
            #pragma unroll
            for (int k = 0; k < D2; ++k) acc = fmaf(xr[k], Wb[k * E + e], acc);
        }
        vals[c] = acc;
        sum += acc;
        ssq = fmaf(acc, acc, ssq);
    }

    #pragma unroll
    for (int o = 16; o; o >>= 1) {
        sum += __shfl_xor_sync(~0u, sum, o);
        ssq += __shfl_xor_sync(~0u, ssq, o);
    }
    const int w = tid >> 5, lane = tid & 31;
    if (lane == 0) { rsum[w] = sum; rssq[w] = ssq; }
    __syncthreads();
    if (tid == 0) {
        float s = 0.f, q = 0.f;
        #pragma unroll
        for (int i = 0; i < 8; ++i) { s += rsum[i]; q += rssq[i]; }
        const float mean = s * (1.f / LNCNT);
        const float var  = fmaf(q, 1.f / LNCNT, -mean * mean);
        s_mean = mean;
        s_rstd = rsqrtf(var + 1e-5f);
    }
    __syncthreads();
    const float mean = s_mean, rstd = s_rstd;

    #pragma unroll
    for (int c = 0; c < 18; ++c) {
        const int idx = tid + c * 256;
        g_a[b * LNCNT + idx] = (vals[c] - mean) * rstd * g0[idx] + b0[idx];
    }
}

// ---------------------------------------------------------------------------
// K2: u = a @ Wg[0:72] + b_g ; v = a @ Wg[72:144]
// 8 rows per block (weight traffic /8), f32x2 over row-pairs (fma /2).
// grid = 1024, block 256 (thread = one h column).
// ---------------------------------------------------------------------------
__global__ __launch_bounds__(256) void k_uv(
    const float* __restrict__ Wg, const float* __restrict__ bg)
{
    __shared__ float sa[E * 8];             // [k][r] interleaved for LDS.64 pairs
    const int m0 = blockIdx.x * 8;
    const int h  = threadIdx.x;

    for (int idx = h; idx < E * 8; idx += 256) {
        const int r = idx / E, k = idx - r * E;
        sa[k * 8 + r] = g_a[(m0 + r) * E + k];
    }
    __syncthreads();

    const float bgh = bg[h];
    u64 uacc[4], vacc[4];
    const u64 bg2 = pk(bgh, bgh);
    const u64 z2  = pk(0.f, 0.f);
    #pragma unroll
    for (int p = 0; p < 4; ++p) { uacc[p] = bg2; vacc[p] = z2; }

    #pragma unroll 8
    for (int k = 0; k < E; ++k) {
        const u64 a01 = *(const u64*)&sa[k * 8 + 0];
        const u64 a23 = *(const u64*)&sa[k * 8 + 2];
        const u64 a45 = *(const u64*)&sa[k * 8 + 4];
        const u64 a67 = *(const u64*)&sa[k * 8 + 6];
        const float w0 = Wg[k * H + h];
        const float w1 = Wg[(E + k) * H + h];
        const u64 w02 = pk(w0, w0);
        const u64 w12 = pk(w1, w1);
        uacc[0] = fma2(a01, w02, uacc[0]);
        uacc[1] = fma2(a23, w02, uacc[1]);
        uacc[2] = fma2(a45, w02, uacc[2]);
        uacc[3] = fma2(a67, w02, uacc[3]);
        vacc[0] = fma2(a01, w12, vacc[0]);
        vacc[1] = fma2(a23, w12, vacc[1]);
        vacc[2] = fma2(a45, w12, vacc[2]);
        vacc[3] = fma2(a67, w12, vacc[3]);
    }

    #pragma unroll
    for (int p = 0; p < 4; ++p) {
        float lo, hi;
        upk(uacc[p], lo, hi);
        g_u[(m0 + 2 * p) * H + h] = lo;
        g_u[(m0 + 2 * p + 1) * H + h] = hi;
        upk(vacc[p], lo, hi);
        g_v[(m0 + 2 * p) * H + h] = lo;
        g_v[(m0 + 2 * p + 1) * H + h] = hi;
    }
}

// ---------------------------------------------------------------------------
// K3: pairwise: for each (b,i): Σ_j LN_H(ELU(u[b,i]+v[b,j])).
// Warp per i (lane = 8 channels, packed as 4 f32x2). 8 warps/block share b.
// γ factored out of the j-loop; block-level reduce over the 8 i's in smem.
// ---------------------------------------------------------------------------
__global__ __launch_bounds__(256) void k_pair(
    const float* __restrict__ lg, const float* __restrict__ lb)
{
    extern __shared__ float sv[];               // [64*256] v[b]; reused for reduce
    const int b    = blockIdx.x >> 3;
    const int ig   = blockIdx.x & 7;
    const int tid  = threadIdx.x;
    const int w    = tid >> 5;
    const int lane = tid & 31;

    // stage v[b]
    {
        const float4* vb = (const float4*)(g_v + b * NN * H);
        float4* s4 = (float4*)sv;
        for (int t = tid; t < NN * H / 4; t += 256) s4[t] = vb[t];
    }

    const int i  = ig * 8 + w;
    const int m  = b * NN + i;
    const int c0 = lane * 8;

    u64 ru2[4];
    {
        const ulonglong2* up = (const ulonglong2*)(g_u + m * H + c0);
        const ulonglong2 p0 = up[0], p1 = up[1];
        ru2[0] = p0.x; ru2[1] = p0.y; ru2[2] = p1.x; ru2[3] = p1.y;
    }
    u64 acc2[4];
    const u64 Z2   = pk(0.f, 0.f);
    const u64 L2E  = pk(1.44269504f, 1.44269504f);
    const u64 NEG1 = pk(-1.f, -1.f);
    #pragma unroll
    for (int p = 0; p < 4; ++p) acc2[p] = Z2;
    float smA = 0.f;

    __syncthreads();

    for (int j = 0; j < NN; ++j) {
        const ulonglong2* vp = (const ulonglong2*)&sv[j * H + c0];
        const ulonglong2 q0 = vp[0], q1 = vp[1];
        u64 v2[4] = {q0.x, q0.y, q1.x, q1.y};

        u64 e2[4];
        #pragma unroll
        for (int p = 0; p < 4; ++p) {
            const u64 t2 = add2(ru2[p], v2[p]);
            const u64 x2 = mul2(t2, L2E);
            float x0, x1, t0, t1, m0f, m1f;
            upk(x2, x0, x1);
            upk(t2, t0, t1);
            const u64 em2 = add2(pk(ex2f(x0), ex2f(x1)), NEG1);
            upk(em2, m0f, m1f);
            // ELU: e = max(t,0) + min(exp(t)-1, 0)   (FMNMX on alu pipe)
            e2[p] = add2(pk(fmaxf(t0, 0.f), fmaxf(t1, 0.f)),
                         pk(fminf(m0f, 0.f), fminf(m1f, 0.f)));
        }

        // per-lane horizontal sums (packed tree)
        u64 se = add2(add2(e2[0], e2[1]), add2(e2[2], e2[3]));
        u64 sq = mul2(e2[0], e2[0]);
        sq = fma2(e2[1], e2[1], sq);
        sq = fma2(e2[2], e2[2], sq);
        sq = fma2(e2[3], e2[3], sq);
        float selo, sehi, sqlo, sqhi;
        upk(se, selo, sehi); upk(sq, sqlo, sqhi);
        float sum = selo + sehi;
        float ssq = sqlo + sqhi;

        #pragma unroll
        for (int o = 16; o; o >>= 1) {
            sum += __shfl_xor_sync(~0u, sum, o);
            ssq += __shfl_xor_sync(~0u, ssq, o);
        }
        const float mean = sum * (1.f / H);
        const float var  = fmaf(ssq, 1.f / H, -mean * mean);
        const float A    = rsqrtf(var + 1e-5f);
        smA = fmaf(mean, A, smA);
        const u64 A2 = pk(A, A);
        #pragma unroll
        for (int p = 0; p < 4; ++p) acc2[p] = fma2(e2[p], A2, acc2[p]);
    }

    // block reduce over the 8 warps: r_c = accE_c - smA, then γ·Σ + 512·β
    __syncthreads();                       // all warps done reading v
    {
        const u64 nsmA = pk(-smA, -smA);
        ulonglong2* dst = (ulonglong2*)&sv[w * H + c0];
        ulonglong2 d0, d1;
        d0.x = add2(acc2[0], nsmA); d0.y = add2(acc2[1], nsmA);
        d1.x = add2(acc2[2], nsmA); d1.y = add2(acc2[3], nsmA);
        dst[0] = d0; dst[1] = d1;
    }
    __syncthreads();
    {
        float s = 0.f;
        #pragma unroll
        for (int ww = 0; ww < 8; ++ww) s += sv[ww * H + tid];
        g_p[blockIdx.x * H + tid] = fmaf(lg[tid], s, 512.f * lb[tid]);
    }
}

// ---------------------------------------------------------------------------
// K4: s[b] = Σ over 8 partials; out = ELU(s @ W_f + b_f). One block per b.
// ---------------------------------------------------------------------------
__global__ __launch_bounds__(256) void k_final(
    const float* __restrict__ Wf, const float* __restrict__ bf,
    float* __restrict__ out)
{
    const int b   = blockIdx.x;
    const int tid = threadIdx.x;
    __shared__ float ss[H];

    float s = 0.f;
    #pragma unroll
    for (int ig = 0; ig < 8; ++ig) s += g_p[(b * 8 + ig) * H + tid];
    ss[tid] = s;
    __syncthreads();

    if (tid < F) {
        float o = bf[tid];
        #pragma unroll 8
        for (int h = 0; h < H; ++h) o = fmaf(ss[h], Wf[h * F + tid], o);
        out[b * F + tid] = (o > 0.f) ? o : expm1f(o);
    }
}

// ---------------------------------------------------------------------------
extern "C" void kernel_launch(void* const* d_in, const int* in_sizes, int n_in,
                              void* d_out, int out_size)
{
    const float* x_a   = (const float*)d_in[0];
    const float* x_b   = (const float*)d_in[1];
    const float* W_a   = (const float*)d_in[2];
    const float* b_a   = (const float*)d_in[3];
    const float* W_b   = (const float*)d_in[4];
    const float* b_b   = (const float*)d_in[5];
    const float* ln0_g = (const float*)d_in[6];
    const float* ln0_b = (const float*)d_in[7];
    const float* W_g   = (const float*)d_in[8];
    const float* b_g   = (const float*)d_in[9];
    const float* lng_g = (const float*)d_in[10];
    const float* lng_b = (const float*)d_in[11];
    const float* W_f   = (const float*)d_in[12];
    const float* b_f   = (const float*)d_in[13];
    float* out = (float*)d_out;

    k_embed_ln<<<B, 256>>>(x_a, x_b, W_a, b_a, W_b, b_b, ln0_g, ln0_b);
    k_uv<<<B * NN / 8, 256>>>(W_g, b_g);

    const size_t smem = NN * H * sizeof(float);   // 64 KB
    cudaFuncSetAttribute(k_pair, cudaFuncAttributeMaxDynamicSharedMemorySize, (int)smem);
    k_pair<<<B * 8, 256, smem>>>(lng_g, lng_b);

    k_final<<<B, 256>>>(W_f, b_f, out);
}

// round 3
// speedup vs baseline: 1.6267x; 1.1324x over previous
#include <cuda_runtime.h>
#include <cuda_bf16.h>

#define B    128
#define N1   32
#define N2   32
#define D1   23
#define D2   13
#define NN   64
#define E    72
#define H    256
#define F    128
#define LNCNT 4608

typedef unsigned long long u64;

// ---- f32x2 packed helpers (sm_103a) ----
__device__ __forceinline__ u64 pk(float lo, float hi) {
    u64 r; asm("mov.b64 %0, {%1,%2};" : "=l"(r) : "f"(lo), "f"(hi)); return r;
}
__device__ __forceinline__ void upk(u64 x, float& lo, float& hi) {
    asm("mov.b64 {%0,%1}, %2;" : "=f"(lo), "=f"(hi) : "l"(x));
}
__device__ __forceinline__ u64 add2(u64 a, u64 b) {
    u64 d; asm("add.rn.f32x2 %0,%1,%2;" : "=l"(d) : "l"(a), "l"(b)); return d;
}
__device__ __forceinline__ u64 mul2(u64 a, u64 b) {
    u64 d; asm("mul.rn.f32x2 %0,%1,%2;" : "=l"(d) : "l"(a), "l"(b)); return d;
}
__device__ __forceinline__ u64 fma2(u64 a, u64 b, u64 c) {
    u64 d; asm("fma.rn.f32x2 %0,%1,%2,%3;" : "=l"(d) : "l"(a), "l"(b), "l"(c)); return d;
}
__device__ __forceinline__ float ex2f(float x) {
    float r; asm("ex2.approx.ftz.f32 %0, %1;" : "=f"(r) : "f"(x)); return r;
}

// Scratch
__device__ float g_a[B * NN * E];
__device__ float g_u[B * NN * H];
__device__ float g_v[B * NN * H];
__device__ float g_p[B * 8 * H];

// ---------------------------------------------------------------------------
// K1: split-embedding + joint LayerNorm over (N,E). One block per b.
// ---------------------------------------------------------------------------
__global__ __launch_bounds__(256) void k_embed_ln(
    const float* __restrict__ xa, const float* __restrict__ xb,
    const float* __restrict__ Wa, const float* __restrict__ ba,
    const float* __restrict__ Wb, const float* __restrict__ bb,
    const float* __restrict__ g0, const float* __restrict__ b0)
{
    const int b   = blockIdx.x;
    const int tid = threadIdx.x;
    __shared__ float rsum[8], rssq[8];
    __shared__ float s_mean, s_rstd;

    float vals[18];
    float sum = 0.f, ssq = 0.f;

    #pragma unroll
    for (int c = 0; c < 18; ++c) {
        const int idx = tid + c * 256;
        const int n = idx / E;
        const int e = idx - n * E;
        float acc;
        if (n < N1) {
            acc = ba[e];
            const float* xr = xa + (b * N1 + n) * D1;
            #pragma unroll
            for (int k = 0; k < D1; ++k) acc = fmaf(xr[k], Wa[k * E + e], acc);
        } else {
            acc = bb[e];
            const float* xr = xb + (b * N2 + (n - N1)) * D2;
            #pragma unroll
            for (int k = 0; k < D2; ++k) acc = fmaf(xr[k], Wb[k * E + e], acc);
        }
        vals[c] = acc;
        sum += acc;
        ssq = fmaf(acc, acc, ssq);
    }

    #pragma unroll
    for (int o = 16; o; o >>= 1) {
        sum += __shfl_xor_sync(~0u, sum, o);
        ssq += __shfl_xor_sync(~0u, ssq, o);
    }
    const int w = tid >> 5, lane = tid & 31;
    if (lane == 0) { rsum[w] = sum; rssq[w] = ssq; }
    __syncthreads();
    if (tid == 0) {
        float s = 0.f, q = 0.f;
        #pragma unroll
        for (int i = 0; i < 8; ++i) { s += rsum[i]; q += rssq[i]; }
        const float mean = s * (1.f / LNCNT);
        const float var  = fmaf(q, 1.f / LNCNT, -mean * mean);
        s_mean = mean;
        s_rstd = rsqrtf(var + 1e-5f);
    }
    __syncthreads();
    const float mean = s_mean, rstd = s_rstd;

    #pragma unroll
    for (int c = 0; c < 18; ++c) {
        const int idx = tid + c * 256;
        g_a[b * LNCNT + idx] = (vals[c] - mean) * rstd * g0[idx] + b0[idx];
    }
}

// ---------------------------------------------------------------------------
// K2: u = a @ Wg[0:72] + b_g ; v = a @ Wg[72:144]. 8 rows/block, f32x2 pairs.
// ---------------------------------------------------------------------------
__global__ __launch_bounds__(256) void k_uv(
    const float* __restrict__ Wg, const float* __restrict__ bg)
{
    __shared__ float sa[E * 8];
    const int m0 = blockIdx.x * 8;
    const int h  = threadIdx.x;

    for (int idx = h; idx < E * 8; idx += 256) {
        const int r = idx / E, k = idx - r * E;
        sa[k * 8 + r] = g_a[(m0 + r) * E + k];
    }
    __syncthreads();

    const float bgh = bg[h];
    u64 uacc[4], vacc[4];
    const u64 bg2 = pk(bgh, bgh);
    const u64 z2  = pk(0.f, 0.f);
    #pragma unroll
    for (int p = 0; p < 4; ++p) { uacc[p] = bg2; vacc[p] = z2; }

    #pragma unroll 8
    for (int k = 0; k < E; ++k) {
        const u64 a01 = *(const u64*)&sa[k * 8 + 0];
        const u64 a23 = *(const u64*)&sa[k * 8 + 2];
        const u64 a45 = *(const u64*)&sa[k * 8 + 4];
        const u64 a67 = *(const u64*)&sa[k * 8 + 6];
        const float w0 = Wg[k * H + h];
        const float w1 = Wg[(E + k) * H + h];
        const u64 w02 = pk(w0, w0);
        const u64 w12 = pk(w1, w1);
        uacc[0] = fma2(a01, w02, uacc[0]);
        uacc[1] = fma2(a23, w02, uacc[1]);
        uacc[2] = fma2(a45, w02, uacc[2]);
        uacc[3] = fma2(a67, w02, uacc[3]);
        vacc[0] = fma2(a01, w12, vacc[0]);
        vacc[1] = fma2(a23, w12, vacc[1]);
        vacc[2] = fma2(a45, w12, vacc[2]);
        vacc[3] = fma2(a67, w12, vacc[3]);
    }

    #pragma unroll
    for (int p = 0; p < 4; ++p) {
        float lo, hi;
        upk(uacc[p], lo, hi);
        g_u[(m0 + 2 * p) * H + h] = lo;
        g_u[(m0 + 2 * p + 1) * H + h] = hi;
        upk(vacc[p], lo, hi);
        g_v[(m0 + 2 * p) * H + h] = lo;
        g_v[(m0 + 2 * p + 1) * H + h] = hi;
    }
}

// ---------------------------------------------------------------------------
// K3: pairwise Σ_j LN_H(ELU(u_i + v_j)). Warp per i, 8 warps/block share b.
// __launch_bounds__(256,3): cap regs so 3 blocks/SM co-reside (6 warps/SMSP)
// to cover the SHFL-butterfly + LDS latency chain.
// ---------------------------------------------------------------------------
__global__ __launch_bounds__(256, 3) void k_pair(
    const float* __restrict__ lg, const float* __restrict__ lb)
{
    extern __shared__ float sv[];               // [64*256] v[b]; reused for reduce
    const int b    = blockIdx.x >> 3;
    const int ig   = blockIdx.x & 7;
    const int tid  = threadIdx.x;
    const int w    = tid >> 5;
    const int lane = tid & 31;

    {
        const float4* vb = (const float4*)(g_v + b * NN * H);
        float4* s4 = (float4*)sv;
        for (int t = tid; t < NN * H / 4; t += 256) s4[t] = vb[t];
    }

    const int i  = ig * 8 + w;
    const int m  = b * NN + i;
    const int c0 = lane * 8;

    u64 ru2[4];
    {
        const ulonglong2* up = (const ulonglong2*)(g_u + m * H + c0);
        const ulonglong2 p0 = up[0], p1 = up[1];
        ru2[0] = p0.x; ru2[1] = p0.y; ru2[2] = p1.x; ru2[3] = p1.y;
    }
    u64 acc2[4];
    const u64 Z2   = pk(0.f, 0.f);
    const u64 L2E  = pk(1.44269504f, 1.44269504f);
    const u64 NEG1 = pk(-1.f, -1.f);
    #pragma unroll
    for (int p = 0; p < 4; ++p) acc2[p] = Z2;
    float smA = 0.f;

    __syncthreads();

    for (int j = 0; j < NN; ++j) {
        const ulonglong2* vp = (const ulonglong2*)&sv[j * H + c0];
        const ulonglong2 q0 = vp[0], q1 = vp[1];
        u64 v2[4] = {q0.x, q0.y, q1.x, q1.y};

        u64 e2[4];
        #pragma unroll
        for (int p = 0; p < 4; ++p) {
            const u64 t2 = add2(ru2[p], v2[p]);
            const u64 x2 = mul2(t2, L2E);
            float x0, x1, t0, t1, m0f, m1f;
            upk(x2, x0, x1);
            upk(t2, t0, t1);
            const u64 em2 = add2(pk(ex2f(x0), ex2f(x1)), NEG1);
            upk(em2, m0f, m1f);
            e2[p] = add2(pk(fmaxf(t0, 0.f), fmaxf(t1, 0.f)),
                         pk(fminf(m0f, 0.f), fminf(m1f, 0.f)));
        }

        u64 se = add2(add2(e2[0], e2[1]), add2(e2[2], e2[3]));
        u64 sq = mul2(e2[0], e2[0]);
        sq = fma2(e2[1], e2[1], sq);
        sq = fma2(e2[2], e2[2], sq);
        sq = fma2(e2[3], e2[3], sq);
        float selo, sehi, sqlo, sqhi;
        upk(se, selo, sehi); upk(sq, sqlo, sqhi);
        float sum = selo + sehi;
        float ssq = sqlo + sqhi;

        #pragma unroll
        for (int o = 16; o; o >>= 1) {
            sum += __shfl_xor_sync(~0u, sum, o);
            ssq += __shfl_xor_sync(~0u, ssq, o);
        }
        const float mean = sum * (1.f / H);
        const float var  = fmaf(ssq, 1.f / H, -mean * mean);
        const float A    = rsqrtf(var + 1e-5f);
        smA = fmaf(mean, A, smA);
        const u64 A2 = pk(A, A);
        #pragma unroll
        for (int p = 0; p < 4; ++p) acc2[p] = fma2(e2[p], A2, acc2[p]);
    }

    __syncthreads();
    {
        const u64 nsmA = pk(-smA, -smA);
        ulonglong2* dst = (ulonglong2*)&sv[w * H + c0];
        ulonglong2 d0, d1;
        d0.x = add2(acc2[0], nsmA); d0.y = add2(acc2[1], nsmA);
        d1.x = add2(acc2[2], nsmA); d1.y = add2(acc2[3], nsmA);
        dst[0] = d0; dst[1] = d1;
    }
    __syncthreads();
    {
        float s = 0.f;
        #pragma unroll
        for (int ww = 0; ww < 8; ++ww) s += sv[ww * H + tid];
        g_p[blockIdx.x * H + tid] = fmaf(lg[tid], s, 512.f * lb[tid]);
    }
}

// ---------------------------------------------------------------------------
// K4: s[b] = Σ partials; out = ELU(s @ W_f + b_f).
// ILP fix: 2 threads per output f (H split in halves), 4 accumulators each
// -> dependent-chain 32 instead of 256.
// ---------------------------------------------------------------------------
__global__ __launch_bounds__(256) void k_final(
    const float* __restrict__ Wf, const float* __restrict__ bf,
    float* __restrict__ out)
{
    const int b   = blockIdx.x;
    const int tid = threadIdx.x;
    __shared__ float ss[H];
    __shared__ float part[F];

    float s = 0.f;
    #pragma unroll
    for (int ig = 0; ig < 8; ++ig) s += g_p[(b * 8 + ig) * H + tid];
    ss[tid] = s;
    __syncthreads();

    const int f    = tid & (F - 1);
    const int half = tid >> 7;
    const int hb   = half * 128;

    float a0 = 0.f, a1 = 0.f, a2 = 0.f, a3 = 0.f;
    #pragma unroll 8
    for (int h = 0; h < 128; h += 4) {
        a0 = fmaf(ss[hb + h + 0], Wf[(hb + h + 0) * F + f], a0);
        a1 = fmaf(ss[hb + h + 1], Wf[(hb + h + 1) * F + f], a1);
        a2 = fmaf(ss[hb + h + 2], Wf[(hb + h + 2) * F + f], a2);
        a3 = fmaf(ss[hb + h + 3], Wf[(hb + h + 3) * F + f], a3);
    }
    const float r = (a0 + a1) + (a2 + a3);

    if (half) part[f] = r;
    __syncthreads();
    if (!half) {
        const float o = bf[f] + r + part[f];
        out[b * F + f] = (o > 0.f) ? o : expm1f(o);
    }
}

// ---------------------------------------------------------------------------
extern "C" void kernel_launch(void* const* d_in, const int* in_sizes, int n_in,
                              void* d_out, int out_size)
{
    const float* x_a   = (const float*)d_in[0];
    const float* x_b   = (const float*)d_in[1];
    const float* W_a   = (const float*)d_in[2];
    const float* b_a   = (const float*)d_in[3];
    const float* W_b   = (const float*)d_in[4];
    const float* b_b   = (const float*)d_in[5];
    const float* ln0_g = (const float*)d_in[6];
    const float* ln0_b = (const float*)d_in[7];
    const float* W_g   = (const float*)d_in[8];
    const float* b_g   = (const float*)d_in[9];
    const float* lng_g = (const float*)d_in[10];
    const float* lng_b = (const float*)d_in[11];
    const float* W_f   = (const float*)d_in[12];
    const float* b_f   = (const float*)d_in[13];
    float* out = (float*)d_out;

    k_embed_ln<<<B, 256>>>(x_a, x_b, W_a, b_a, W_b, b_b, ln0_g, ln0_b);
    k_uv<<<B * NN / 8, 256>>>(W_g, b_g);

    const size_t smem = NN * H * sizeof(float);   // 64 KB
    cudaFuncSetAttribute(k_pair, cudaFuncAttributeMaxDynamicSharedMemorySize, (int)smem);
    k_pair<<<B * 8, 256, smem>>>(lng_g, lng_b);

    k_final<<<B, 256>>>(W_f, b_f, out);
}

// round 4
// speedup vs baseline: 1.6632x; 1.0225x over previous
#include <cuda_runtime.h>
#include <cuda_bf16.h>

#define B    128
#define N1   32
#define N2   32
#define D1   23
#define D2   13
#define NN   64
#define E    72
#define H    256
#define F    128
#define LNCNT 4608

typedef unsigned long long u64;

// ---- f32x2 packed helpers (sm_103a) ----
__device__ __forceinline__ u64 pk(float lo, float hi) {
    u64 r; asm("mov.b64 %0, {%1,%2};" : "=l"(r) : "f"(lo), "f"(hi)); return r;
}
__device__ __forceinline__ void upk(u64 x, float& lo, float& hi) {
    asm("mov.b64 {%0,%1}, %2;" : "=f"(lo), "=f"(hi) : "l"(x));
}
__device__ __forceinline__ u64 add2(u64 a, u64 b) {
    u64 d; asm("add.rn.f32x2 %0,%1,%2;" : "=l"(d) : "l"(a), "l"(b)); return d;
}
__device__ __forceinline__ u64 mul2(u64 a, u64 b) {
    u64 d; asm("mul.rn.f32x2 %0,%1,%2;" : "=l"(d) : "l"(a), "l"(b)); return d;
}
__device__ __forceinline__ u64 fma2(u64 a, u64 b, u64 c) {
    u64 d; asm("fma.rn.f32x2 %0,%1,%2,%3;" : "=l"(d) : "l"(a), "l"(b), "l"(c)); return d;
}
__device__ __forceinline__ float ex2f(float x) {
    float r; asm("ex2.approx.ftz.f32 %0, %1;" : "=f"(r) : "f"(x)); return r;
}
__device__ __forceinline__ u64 shfl_xor_u64(u64 x, int o) {
    float lo, hi; upk(x, lo, hi);
    lo = __shfl_xor_sync(~0u, lo, o);
    hi = __shfl_xor_sync(~0u, hi, o);
    return pk(lo, hi);
}

// Scratch
__device__ float g_a[B * NN * E];
__device__ float g_u[B * NN * H];
__device__ float g_v[B * NN * H];
__device__ float g_p[B * 8 * H];

// ---------------------------------------------------------------------------
// K1: split-embedding + joint LayerNorm over (N,E). One block per b.
// ---------------------------------------------------------------------------
__global__ __launch_bounds__(256) void k_embed_ln(
    const float* __restrict__ xa, const float* __restrict__ xb,
    const float* __restrict__ Wa, const float* __restrict__ ba,
    const float* __restrict__ Wb, const float* __restrict__ bb,
    const float* __restrict__ g0, const float* __restrict__ b0)
{
    const int b   = blockIdx.x;
    const int tid = threadIdx.x;
    __shared__ float rsum[8], rssq[8];
    __shared__ float s_mean, s_rstd;

    float vals[18];
    float sum = 0.f, ssq = 0.f;

    #pragma unroll
    for (int c = 0; c < 18; ++c) {
        const int idx = tid + c * 256;
        const int n = idx / E;
        const int e = idx - n * E;
        float acc;
        if (n < N1) {
            acc = ba[e];
            const float* xr = xa + (b * N1 + n) * D1;
            #pragma unroll
            for (int k = 0; k < D1; ++k) acc = fmaf(xr[k], Wa[k * E + e], acc);
        } else {
            acc = bb[e];
            const float* xr = xb + (b * N2 + (n - N1)) * D2;
            #pragma unroll
            for (int k = 0; k < D2; ++k) acc = fmaf(xr[k], Wb[k * E + e], acc);
        }
        vals[c] = acc;
        sum += acc;
        ssq = fmaf(acc, acc, ssq);
    }

    #pragma unroll
    for (int o = 16; o; o >>= 1) {
        sum += __shfl_xor_sync(~0u, sum, o);
        ssq += __shfl_xor_sync(~0u, ssq, o);
    }
    const int w = tid >> 5, lane = tid & 31;
    if (lane == 0) { rsum[w] = sum; rssq[w] = ssq; }
    __syncthreads();
    if (tid == 0) {
        float s = 0.f, q = 0.f;
        #pragma unroll
        for (int i = 0; i < 8; ++i) { s += rsum[i]; q += rssq[i]; }
        const float mean = s * (1.f / LNCNT);
        const float var  = fmaf(q, 1.f / LNCNT, -mean * mean);
        s_mean = mean;
        s_rstd = rsqrtf(var + 1e-5f);
    }
    __syncthreads();
    const float mean = s_mean, rstd = s_rstd;

    #pragma unroll
    for (int c = 0; c < 18; ++c) {
        const int idx = tid + c * 256;
        g_a[b * LNCNT + idx] = (vals[c] - mean) * rstd * g0[idx] + b0[idx];
    }
}

// ---------------------------------------------------------------------------
// K2: u = a @ Wg[0:72] + b_g ; v = a @ Wg[72:144].
// 16 rows/block (weight L2 traffic halved vs 8), f32x2 over row-pairs,
// LDS.128 a-loads. grid = 512.
// ---------------------------------------------------------------------------
__global__ __launch_bounds__(256) void k_uv(
    const float* __restrict__ Wg, const float* __restrict__ bg)
{
    __shared__ float sa[E * 16];            // [k][r], r = 0..15
    const int m0 = blockIdx.x * 16;
    const int h  = threadIdx.x;

    for (int idx = h; idx < E * 16; idx += 256) {
        const int r = idx >> 6;             // idx / 64? no: E*16=1152; use div
        const int rr = idx / E, k = idx - rr * E;
        (void)r;
        sa[k * 16 + rr] = g_a[(m0 + rr) * E + k];
    }
    __syncthreads();

    const float bgh = bg[h];
    u64 uacc[8], vacc[8];
    const u64 bg2 = pk(bgh, bgh);
    const u64 z2  = pk(0.f, 0.f);
    #pragma unroll
    for (int p = 0; p < 8; ++p) { uacc[p] = bg2; vacc[p] = z2; }

    #pragma unroll 4
    for (int k = 0; k < E; ++k) {
        const ulonglong2* ar = (const ulonglong2*)&sa[k * 16];
        const ulonglong2 q0 = ar[0], q1 = ar[1], q2 = ar[2], q3 = ar[3];
        const u64 av[8] = {q0.x, q0.y, q1.x, q1.y, q2.x, q2.y, q3.x, q3.y};
        const float w0 = Wg[k * H + h];
        const float w1 = Wg[(E + k) * H + h];
        const u64 w02 = pk(w0, w0);
        const u64 w12 = pk(w1, w1);
        #pragma unroll
        for (int p = 0; p < 8; ++p) {
            uacc[p] = fma2(av[p], w02, uacc[p]);
            vacc[p] = fma2(av[p], w12, vacc[p]);
        }
    }

    #pragma unroll
    for (int p = 0; p < 8; ++p) {
        float lo, hi;
        upk(uacc[p], lo, hi);
        g_u[(m0 + 2 * p) * H + h] = lo;
        g_u[(m0 + 2 * p + 1) * H + h] = hi;
        upk(vacc[p], lo, hi);
        g_v[(m0 + 2 * p) * H + h] = lo;
        g_v[(m0 + 2 * p + 1) * H + h] = hi;
    }
}

// ---------------------------------------------------------------------------
// K3: pairwise Σ_j LN_H(ELU(u_i + v_j)). Warp per i, 8 warps/block share b.
// Half-warp j-split: lanes 0-15 even j, 16-31 odd j; 16 channels/lane.
// v stored in smem with granule swizzle so each LDS.128 is conflict-free:
//   channel c of row j  ->  float offset j*256 + ((c>>2)&3)*64 + (c>>4)*4 + (c&3)
// ELU via min(e^t - 1, max(t,0)).
// ---------------------------------------------------------------------------
__global__ __launch_bounds__(256, 3) void k_pair(
    const float* __restrict__ lg, const float* __restrict__ lb)
{
    extern __shared__ float sv[];               // 64KB swizzled v; reused for reduce
    const int b    = blockIdx.x >> 3;
    const int ig   = blockIdx.x & 7;
    const int tid  = threadIdx.x;
    const int w    = tid >> 5;
    const int lane = tid & 31;
    const int half = lane >> 4;
    const int sub  = lane & 15;
    const int ch0  = sub * 16;

    // stage v[b] with swizzle
    {
        const float4* vb = (const float4*)(g_v + b * NN * H);
        float4* s4 = (float4*)sv;
        #pragma unroll
        for (int c = 0; c < 16; ++c) {
            const int g = tid + c * 256;        // < 4096
            const int j = g >> 6;
            const int q = g & 63;               // float4 within row; channels 4q..4q+3
            s4[j * 64 + (q & 3) * 16 + (q >> 2)] = vb[g];
        }
    }

    const int i = ig * 8 + w;
    const int m = b * NN + i;

    u64 ru2[8];
    {
        const ulonglong2* uu = (const ulonglong2*)(g_u + m * H + ch0);
        const ulonglong2 a0 = uu[0], a1 = uu[1], a2 = uu[2], a3 = uu[3];
        ru2[0] = a0.x; ru2[1] = a0.y; ru2[2] = a1.x; ru2[3] = a1.y;
        ru2[4] = a2.x; ru2[5] = a2.y; ru2[6] = a3.x; ru2[7] = a3.y;
    }
    u64 acc2[8];
    const u64 L2E  = pk(1.44269504f, 1.44269504f);
    const u64 NEG1 = pk(-1.f, -1.f);
    #pragma unroll
    for (int p = 0; p < 8; ++p) acc2[p] = 0ull;
    float smA = 0.f;

    __syncthreads();

    #pragma unroll 2
    for (int s = 0; s < 32; ++s) {
        const int jj = 2 * s + half;
        const ulonglong2* vr = (const ulonglong2*)(sv + jj * 256);

        u64 e2[8];
        #pragma unroll
        for (int t = 0; t < 4; ++t) {
            const ulonglong2 q = vr[t * 16 + sub];   // conflict-free LDS.128
            const u64 vv[2] = {q.x, q.y};
            #pragma unroll
            for (int k = 0; k < 2; ++k) {
                const int p = 2 * t + k;
                const u64 t2 = add2(ru2[p], vv[k]);
                const u64 x2 = mul2(t2, L2E);
                float x0, x1, t0, t1, m0f, m1f;
                upk(x2, x0, x1);
                const u64 em2 = add2(pk(ex2f(x0), ex2f(x1)), NEG1);
                upk(t2, t0, t1);
                upk(em2, m0f, m1f);
                // ELU = min(e^t - 1, max(t, 0))
                e2[p] = pk(fminf(m0f, fmaxf(t0, 0.f)),
                           fminf(m1f, fmaxf(t1, 0.f)));
            }
        }

        // per-lane horizontal (16 channels)
        u64 se = add2(add2(add2(e2[0], e2[1]), add2(e2[2], e2[3])),
                      add2(add2(e2[4], e2[5]), add2(e2[6], e2[7])));
        u64 sq = mul2(e2[0], e2[0]);
        #pragma unroll
        for (int p = 1; p < 8; ++p) sq = fma2(e2[p], e2[p], sq);
        float selo, sehi, sqlo, sqhi;
        upk(se, selo, sehi); upk(sq, sqlo, sqhi);
        float sum = selo + sehi;
        float ssq = sqlo + sqhi;

        // butterfly within 16-lane half (offsets 8,4,2,1)
        #pragma unroll
        for (int o = 8; o; o >>= 1) {
            sum += __shfl_xor_sync(~0u, sum, o);
            ssq += __shfl_xor_sync(~0u, ssq, o);
        }
        const float mean = sum * (1.f / H);
        const float var  = fmaf(ssq, 1.f / H, -mean * mean);
        const float A    = rsqrtf(var + 1e-5f);
        smA = fmaf(mean, A, smA);
        const u64 A2 = pk(A, A);
        #pragma unroll
        for (int p = 0; p < 8; ++p) acc2[p] = fma2(e2[p], A2, acc2[p]);
    }

    // merge even/odd-j halves
    #pragma unroll
    for (int p = 0; p < 8; ++p) acc2[p] = add2(acc2[p], shfl_xor_u64(acc2[p], 16));
    smA += __shfl_xor_sync(~0u, smA, 16);

    __syncthreads();                       // all warps done reading v
    if (half == 0) {
        const u64 nsmA = pk(-smA, -smA);
        u64* dst = (u64*)&sv[w * H + ch0];
        #pragma unroll
        for (int p = 0; p < 8; ++p) dst[p] = add2(acc2[p], nsmA);
    }
    __syncthreads();
    {
        float s = 0.f;
        #pragma unroll
        for (int ww = 0; ww < 8; ++ww) s += sv[ww * H + tid];
        g_p[blockIdx.x * H + tid] = fmaf(lg[tid], s, 512.f * lb[tid]);
    }
}

// ---------------------------------------------------------------------------
// K4: s[b] = Σ 8 partials; out = ELU(s @ W_f + b_f).
// 512 threads: 4 threads per output f (64-h segments, 4 accs -> chain 16).
// ---------------------------------------------------------------------------
__global__ __launch_bounds__(512) void k_final(
    const float* __restrict__ Wf, const float* __restrict__ bf,
    float* __restrict__ out)
{
    const int b   = blockIdx.x;
    const int tid = threadIdx.x;
    __shared__ float ss[H];
    __shared__ float part[3 * F];

    if (tid < H) {
        float s = 0.f;
        #pragma unroll
        for (int ig = 0; ig < 8; ++ig) s += g_p[(b * 8 + ig) * H + tid];
        ss[tid] = s;
    }
    __syncthreads();

    const int f   = tid & (F - 1);
    const int seg = tid >> 7;               // 0..3
    const int hb  = seg * 64;

    float a0 = 0.f, a1 = 0.f, a2 = 0.f, a3 = 0.f;
    #pragma unroll 4
    for (int hh = 0; hh < 64; hh += 4) {
        a0 = fmaf(ss[hb + hh + 0], Wf[(hb + hh + 0) * F + f], a0);
        a1 = fmaf(ss[hb + hh + 1], Wf[(hb + hh + 1) * F + f], a1);
        a2 = fmaf(ss[hb + hh + 2], Wf[(hb + hh + 2) * F + f], a2);
        a3 = fmaf(ss[hb + hh + 3], Wf[(hb + hh + 3) * F + f], a3);
    }
    const float r = (a0 + a1) + (a2 + a3);

    if (seg) part[(seg - 1) * F + f] = r;
    __syncthreads();
    if (seg == 0) {
        const float o = bf[f] + r + part[f] + part[F + f] + part[2 * F + f];
        out[b * F + f] = (o > 0.f) ? o : expm1f(o);
    }
}

// ---------------------------------------------------------------------------
extern "C" void kernel_launch(void* const* d_in, const int* in_sizes, int n_in,
                              void* d_out, int out_size)
{
    const float* x_a   = (const float*)d_in[0];
    const float* x_b   = (const float*)d_in[1];
    const float* W_a   = (const float*)d_in[2];
    const float* b_a   = (const float*)d_in[3];
    const float* W_b   = (const float*)d_in[4];
    const float* b_b   = (const float*)d_in[5];
    const float* ln0_g = (const float*)d_in[6];
    const float* ln0_b = (const float*)d_in[7];
    const float* W_g   = (const float*)d_in[8];
    const float* b_g   = (const float*)d_in[9];
    const float* lng_g = (const float*)d_in[10];
    const float* lng_b = (const float*)d_in[11];
    const float* W_f   = (const float*)d_in[12];
    const float* b_f   = (const float*)d_in[13];
    float* out = (float*)d_out;

    k_embed_ln<<<B, 256>>>(x_a, x_b, W_a, b_a, W_b, b_b, ln0_g, ln0_b);
    k_uv<<<B * NN / 16, 256>>>(W_g, b_g);

    const size_t smem = NN * H * sizeof(float);   // 64 KB
    cudaFuncSetAttribute(k_pair, cudaFuncAttributeMaxDynamicSharedMemorySize, (int)smem);
    k_pair<<<B * 8, 256, smem>>>(lng_g, lng_b);

    k_final<<<B, 512>>>(W_f, b_f, out);
}

// round 5
// speedup vs baseline: 1.7761x; 1.0679x over previous
#include <cuda_runtime.h>
#include <cuda_bf16.h>

#define B    128
#define N1   32
#define N2   32
#define D1   23
#define D2   13
#define NN   64
#define E    72
#define H    256
#define F    128
#define LNCNT 4608

typedef unsigned long long u64;

// ---- f32x2 packed helpers (sm_103a) ----
__device__ __forceinline__ u64 pk(float lo, float hi) {
    u64 r; asm("mov.b64 %0, {%1,%2};" : "=l"(r) : "f"(lo), "f"(hi)); return r;
}
__device__ __forceinline__ void upk(u64 x, float& lo, float& hi) {
    asm("mov.b64 {%0,%1}, %2;" : "=f"(lo), "=f"(hi) : "l"(x));
}
__device__ __forceinline__ u64 add2(u64 a, u64 b) {
    u64 d; asm("add.rn.f32x2 %0,%1,%2;" : "=l"(d) : "l"(a), "l"(b)); return d;
}
__device__ __forceinline__ u64 mul2(u64 a, u64 b) {
    u64 d; asm("mul.rn.f32x2 %0,%1,%2;" : "=l"(d) : "l"(a), "l"(b)); return d;
}
__device__ __forceinline__ u64 fma2(u64 a, u64 b, u64 c) {
    u64 d; asm("fma.rn.f32x2 %0,%1,%2,%3;" : "=l"(d) : "l"(a), "l"(b), "l"(c)); return d;
}
__device__ __forceinline__ u64 shfl_xor_u64(u64 x, int o) {
    float lo, hi; upk(x, lo, hi);
    lo = __shfl_xor_sync(~0u, lo, o);
    hi = __shfl_xor_sync(~0u, hi, o);
    return pk(lo, hi);
}

// Fused packed ELU: e = min(max(t,0), e^t - 1), t = u + v  (one asm block so
// ptxas coalesces pair movs instead of materializing them per op).
__device__ __forceinline__ u64 elu2(u64 u2, u64 v2, u64 l2e, u64 neg1) {
    u64 e;
    asm("{\n\t"
        ".reg .b64 t2, x2, em2;\n\t"
        ".reg .f32 t0, t1, x0, x1, m0, m1, r0, r1;\n\t"
        "add.rn.f32x2 t2, %1, %2;\n\t"
        "mul.rn.f32x2 x2, t2, %3;\n\t"
        "mov.b64 {x0,x1}, x2;\n\t"
        "ex2.approx.ftz.f32 x0, x0;\n\t"
        "ex2.approx.ftz.f32 x1, x1;\n\t"
        "mov.b64 x2, {x0,x1};\n\t"
        "add.rn.f32x2 em2, x2, %4;\n\t"
        "mov.b64 {m0,m1}, em2;\n\t"
        "mov.b64 {t0,t1}, t2;\n\t"
        "max.f32 r0, t0, 0f00000000;\n\t"
        "max.f32 r1, t1, 0f00000000;\n\t"
        "min.f32 r0, r0, m0;\n\t"
        "min.f32 r1, r1, m1;\n\t"
        "mov.b64 %0, {r0,r1};\n\t"
        "}" : "=l"(e) : "l"(u2), "l"(v2), "l"(l2e), "l"(neg1));
    return e;
}

// Scratch
__device__ float g_a[B * NN * E];
__device__ float g_u[B * NN * H];
__device__ float g_v[B * NN * H];
__device__ float g_p[B * 8 * H];

// ---------------------------------------------------------------------------
// K1: split-embedding + joint LayerNorm over (N,E). One block per b.
// ---------------------------------------------------------------------------
__global__ __launch_bounds__(256) void k_embed_ln(
    const float* __restrict__ xa, const float* __restrict__ xb,
    const float* __restrict__ Wa, const float* __restrict__ ba,
    const float* __restrict__ Wb, const float* __restrict__ bb,
    const float* __restrict__ g0, const float* __restrict__ b0)
{
    const int b   = blockIdx.x;
    const int tid = threadIdx.x;
    __shared__ float rsum[8], rssq[8];
    __shared__ float s_mean, s_rstd;

    float vals[18];
    float sum = 0.f, ssq = 0.f;

    #pragma unroll
    for (int c = 0; c < 18; ++c) {
        const int idx = tid + c * 256;
        const int n = idx / E;
        const int e = idx - n * E;
        float acc;
        if (n < N1) {
            acc = ba[e];
            const float* xr = xa + (b * N1 + n) * D1;
            #pragma unroll
            for (int k = 0; k < D1; ++k) acc = fmaf(xr[k], Wa[k * E + e], acc);
        } else {
            acc = bb[e];
            const float* xr = xb + (b * N2 + (n - N1)) * D2;
            #pragma unroll
            for (int k = 0; k < D2; ++k) acc = fmaf(xr[k], Wb[k * E + e], acc);
        }
        vals[c] = acc;
        sum += acc;
        ssq = fmaf(acc, acc, ssq);
    }

    #pragma unroll
    for (int o = 16; o; o >>= 1) {
        sum += __shfl_xor_sync(~0u, sum, o);
        ssq += __shfl_xor_sync(~0u, ssq, o);
    }
    const int w = tid >> 5, lane = tid & 31;
    if (lane == 0) { rsum[w] = sum; rssq[w] = ssq; }
    __syncthreads();
    if (tid == 0) {
        float s = 0.f, q = 0.f;
        #pragma unroll
        for (int i = 0; i < 8; ++i) { s += rsum[i]; q += rssq[i]; }
        const float mean = s * (1.f / LNCNT);
        const float var  = fmaf(q, 1.f / LNCNT, -mean * mean);
        s_mean = mean;
        s_rstd = rsqrtf(var + 1e-5f);
    }
    __syncthreads();
    const float mean = s_mean, rstd = s_rstd;

    #pragma unroll
    for (int c = 0; c < 18; ++c) {
        const int idx = tid + c * 256;
        g_a[b * LNCNT + idx] = (vals[c] - mean) * rstd * g0[idx] + b0[idx];
    }
}

// ---------------------------------------------------------------------------
// K2: u = a @ Wg[0:72] + b_g ; v = a @ Wg[72:144]. 16 rows/block, f32x2.
// ---------------------------------------------------------------------------
__global__ __launch_bounds__(256) void k_uv(
    const float* __restrict__ Wg, const float* __restrict__ bg)
{
    __shared__ float sa[E * 16];
    const int m0 = blockIdx.x * 16;
    const int h  = threadIdx.x;

    for (int idx = h; idx < E * 16; idx += 256) {
        const int rr = idx / E, k = idx - rr * E;
        sa[k * 16 + rr] = g_a[(m0 + rr) * E + k];
    }
    __syncthreads();

    const float bgh = bg[h];
    u64 uacc[8], vacc[8];
    const u64 bg2 = pk(bgh, bgh);
    #pragma unroll
    for (int p = 0; p < 8; ++p) { uacc[p] = bg2; vacc[p] = 0ull; }

    #pragma unroll 4
    for (int k = 0; k < E; ++k) {
        const ulonglong2* ar = (const ulonglong2*)&sa[k * 16];
        const ulonglong2 q0 = ar[0], q1 = ar[1], q2 = ar[2], q3 = ar[3];
        const u64 av[8] = {q0.x, q0.y, q1.x, q1.y, q2.x, q2.y, q3.x, q3.y};
        const float w0 = Wg[k * H + h];
        const float w1 = Wg[(E + k) * H + h];
        const u64 w02 = pk(w0, w0);
        const u64 w12 = pk(w1, w1);
        #pragma unroll
        for (int p = 0; p < 8; ++p) {
            uacc[p] = fma2(av[p], w02, uacc[p]);
            vacc[p] = fma2(av[p], w12, vacc[p]);
        }
    }

    #pragma unroll
    for (int p = 0; p < 8; ++p) {
        float lo, hi;
        upk(uacc[p], lo, hi);
        g_u[(m0 + 2 * p) * H + h] = lo;
        g_u[(m0 + 2 * p + 1) * H + h] = hi;
        upk(vacc[p], lo, hi);
        g_v[(m0 + 2 * p) * H + h] = lo;
        g_v[(m0 + 2 * p + 1) * H + h] = hi;
    }
}

// ---------------------------------------------------------------------------
// K3: pairwise Σ_j LN_H(ELU(u_i + v_j)). Warp per i, 8 warps/block share b.
// Half-warp j-split (lanes 0-15 even j, 16-31 odd j; 16 ch/lane),
// swizzled smem for conflict-free LDS.128, depth-2 software pipeline:
// two j-pair stages in flight, interleaved butterflies.
// ---------------------------------------------------------------------------
__global__ __launch_bounds__(256, 2) void k_pair(
    const float* __restrict__ lg, const float* __restrict__ lb)
{
    extern __shared__ float sv[];               // 64KB swizzled v; reused for reduce
    const int b    = blockIdx.x >> 3;
    const int ig   = blockIdx.x & 7;
    const int tid  = threadIdx.x;
    const int w    = tid >> 5;
    const int lane = tid & 31;
    const int half = lane >> 4;
    const int sub  = lane & 15;
    const int ch0  = sub * 16;

    // stage v[b] with granule swizzle:
    // float4 q of row j -> sv4[j*64 + (q&3)*16 + (q>>2)]
    {
        const float4* vb = (const float4*)(g_v + b * NN * H);
        float4* s4 = (float4*)sv;
        #pragma unroll
        for (int c = 0; c < 16; ++c) {
            const int g = tid + c * 256;
            const int j = g >> 6;
            const int q = g & 63;
            s4[j * 64 + (q & 3) * 16 + (q >> 2)] = vb[g];
        }
    }

    const int i = ig * 8 + w;
    const int m = b * NN + i;

    u64 ru2[8];
    {
        const ulonglong2* uu = (const ulonglong2*)(g_u + m * H + ch0);
        const ulonglong2 a0 = uu[0], a1 = uu[1], a2 = uu[2], a3 = uu[3];
        ru2[0] = a0.x; ru2[1] = a0.y; ru2[2] = a1.x; ru2[3] = a1.y;
        ru2[4] = a2.x; ru2[5] = a2.y; ru2[6] = a3.x; ru2[7] = a3.y;
    }
    u64 acc2[8];
    const u64 L2E  = pk(1.44269504f, 1.44269504f);
    const u64 NEG1 = pk(-1.f, -1.f);
    #pragma unroll
    for (int p = 0; p < 8; ++p) acc2[p] = 0ull;
    float smA = 0.f;

    __syncthreads();

    u64 e2A[8], e2B[8];
    float sumA, ssqA, sumB, ssqB;

    #define LN_STAGE(EE, SUM, SSQ, JJ) {                                      \
        const ulonglong2* vr = (const ulonglong2*)(sv + (JJ) * 256);          \
        {                                                                     \
            const ulonglong2 q0 = vr[sub];                                    \
            const ulonglong2 q1 = vr[16 + sub];                               \
            const ulonglong2 q2 = vr[32 + sub];                               \
            const ulonglong2 q3 = vr[48 + sub];                               \
            EE[0] = elu2(ru2[0], q0.x, L2E, NEG1);                            \
            EE[1] = elu2(ru2[1], q0.y, L2E, NEG1);                            \
            EE[2] = elu2(ru2[2], q1.x, L2E, NEG1);                            \
            EE[3] = elu2(ru2[3], q1.y, L2E, NEG1);                            \
            EE[4] = elu2(ru2[4], q2.x, L2E, NEG1);                            \
            EE[5] = elu2(ru2[5], q2.y, L2E, NEG1);                            \
            EE[6] = elu2(ru2[6], q3.x, L2E, NEG1);                            \
            EE[7] = elu2(ru2[7], q3.y, L2E, NEG1);                            \
        }                                                                     \
        u64 se = add2(add2(add2(EE[0], EE[1]), add2(EE[2], EE[3])),           \
                      add2(add2(EE[4], EE[5]), add2(EE[6], EE[7])));          \
        u64 sq = mul2(EE[0], EE[0]);                                          \
        sq = fma2(EE[1], EE[1], sq); sq = fma2(EE[2], EE[2], sq);             \
        sq = fma2(EE[3], EE[3], sq); sq = fma2(EE[4], EE[4], sq);             \
        sq = fma2(EE[5], EE[5], sq); sq = fma2(EE[6], EE[6], sq);             \
        sq = fma2(EE[7], EE[7], sq);                                          \
        float selo, sehi, sqlo, sqhi;                                         \
        upk(se, selo, sehi); upk(sq, sqlo, sqhi);                             \
        SUM = selo + sehi; SSQ = sqlo + sqhi; }

    #pragma unroll 2
    for (int sI = 0; sI < 32; sI += 2) {
        LN_STAGE(e2A, sumA, ssqA, 2 * sI + half);
        LN_STAGE(e2B, sumB, ssqB, 2 * (sI + 1) + half);

        // interleaved independent butterflies (offsets 8,4,2,1 within halves)
        #pragma unroll
        for (int o = 8; o; o >>= 1) {
            sumA += __shfl_xor_sync(~0u, sumA, o);
            sumB += __shfl_xor_sync(~0u, sumB, o);
            ssqA += __shfl_xor_sync(~0u, ssqA, o);
            ssqB += __shfl_xor_sync(~0u, ssqB, o);
        }
        const float meanA = sumA * (1.f / H);
        const float meanB = sumB * (1.f / H);
        const float varA  = fmaf(ssqA, 1.f / H, -meanA * meanA);
        const float varB  = fmaf(ssqB, 1.f / H, -meanB * meanB);
        const float AA    = rsqrtf(varA + 1e-5f);
        const float AB    = rsqrtf(varB + 1e-5f);
        smA = fmaf(meanA, AA, smA);
        smA = fmaf(meanB, AB, smA);
        const u64 AA2 = pk(AA, AA);
        const u64 AB2 = pk(AB, AB);
        #pragma unroll
        for (int p = 0; p < 8; ++p) {
            acc2[p] = fma2(e2A[p], AA2, acc2[p]);
            acc2[p] = fma2(e2B[p], AB2, acc2[p]);
        }
    }
    #undef LN_STAGE

    // merge even/odd-j halves
    #pragma unroll
    for (int p = 0; p < 8; ++p) acc2[p] = add2(acc2[p], shfl_xor_u64(acc2[p], 16));
    smA += __shfl_xor_sync(~0u, smA, 16);

    __syncthreads();                       // all warps done reading v
    if (half == 0) {
        const u64 nsmA = pk(-smA, -smA);
        u64* dst = (u64*)&sv[w * H + ch0];
        #pragma unroll
        for (int p = 0; p < 8; ++p) dst[p] = add2(acc2[p], nsmA);
    }
    __syncthreads();
    {
        float s = 0.f;
        #pragma unroll
        for (int ww = 0; ww < 8; ++ww) s += sv[ww * H + tid];
        g_p[blockIdx.x * H + tid] = fmaf(lg[tid], s, 512.f * lb[tid]);
    }
}

// ---------------------------------------------------------------------------
// K4: s[b] = Σ 8 partials; out = ELU(s @ W_f + b_f).
// 4-way F-split: 512 blocks, 256 thr. Warp w = h-segment [w*32,w*32+32),
// lane = local f. 8-warp combine via smem.
// ---------------------------------------------------------------------------
__global__ __launch_bounds__(256) void k_final(
    const float* __restrict__ Wf, const float* __restrict__ bf,
    float* __restrict__ out)
{
    const int bid  = blockIdx.x;
    const int b    = bid >> 2;
    const int fq   = bid & 3;
    const int tid  = threadIdx.x;
    const int w    = tid >> 5;
    const int lane = tid & 31;
    __shared__ float ss[H];
    __shared__ float part[8][32];

    {
        float s = 0.f;
        #pragma unroll
        for (int ig = 0; ig < 8; ++ig) s += g_p[(b * 8 + ig) * H + tid];
        ss[tid] = s;
    }
    __syncthreads();

    const int f  = fq * 32 + lane;
    const int h0 = w * 32;
    float a0 = 0.f, a1 = 0.f, a2 = 0.f, a3 = 0.f;
    #pragma unroll
    for (int hh = 0; hh < 32; hh += 4) {
        a0 = fmaf(ss[h0 + hh + 0], Wf[(h0 + hh + 0) * F + f], a0);
        a1 = fmaf(ss[h0 + hh + 1], Wf[(h0 + hh + 1) * F + f], a1);
        a2 = fmaf(ss[h0 + hh + 2], Wf[(h0 + hh + 2) * F + f], a2);
        a3 = fmaf(ss[h0 + hh + 3], Wf[(h0 + hh + 3) * F + f], a3);
    }
    part[w][lane] = (a0 + a1) + (a2 + a3);
    __syncthreads();

    if (w == 0) {
        float o = bf[f];
        #pragma unroll
        for (int k = 0; k < 8; ++k) o += part[k][lane];
        out[b * F + f] = (o > 0.f) ? o : expm1f(o);
    }
}

// ---------------------------------------------------------------------------
extern "C" void kernel_launch(void* const* d_in, const int* in_sizes, int n_in,
                              void* d_out, int out_size)
{
    const float* x_a   = (const float*)d_in[0];
    const float* x_b   = (const float*)d_in[1];
    const float* W_a   = (const float*)d_in[2];
    const float* b_a   = (const float*)d_in[3];
    const float* W_b   = (const float*)d_in[4];
    const float* b_b   = (const float*)d_in[5];
    const float* ln0_g = (const float*)d_in[6];
    const float* ln0_b = (const float*)d_in[7];
    const float* W_g   = (const float*)d_in[8];
    const float* b_g   = (const float*)d_in[9];
    const float* lng_g = (const float*)d_in[10];
    const float* lng_b = (const float*)d_in[11];
    const float* W_f   = (const float*)d_in[12];
    const float* b_f   = (const float*)d_in[13];
    float* out = (float*)d_out;

    k_embed_ln<<<B, 256>>>(x_a, x_b, W_a, b_a, W_b, b_b, ln0_g, ln0_b);
    k_uv<<<B * NN / 16, 256>>>(W_g, b_g);

    const size_t smem = NN * H * sizeof(float);   // 64 KB
    cudaFuncSetAttribute(k_pair, cudaFuncAttributeMaxDynamicSharedMemorySize, (int)smem);
    k_pair<<<B * 8, 256, smem>>>(lng_g, lng_b);

    k_final<<<B * 4, 256>>>(W_f, b_f, out);
}